// round 12
// baseline (speedup 1.0000x reference)
#include <cuda_runtime.h>

#define NN 20000
#define NE 400000
#define FD 64
#define CT 64
#define HD 128
#define TS 6
#define KD 67      // F + 3 label channels
#define KP 68      // padded to multiple of 4
#define NG 6       // concurrent snapshot groups
#define EC 96      // ELL row capacity (in-degree ~ Poisson(20); P(>96)~1e-30)
#define LM 256     // top-node neighbor list cap

// ---------------- scratch (static device globals; no allocation) -------------
__device__ int   g_flagA[NG][NN];
__device__ int   g_flagB[NG][NN];
__device__ int   g_isc[NG][NN];
__device__ int   g_cnt[NG][NN];
__device__ int   g_ell[NG][NN * EC];   // ELL src lists (row i at i*EC)
__device__ float g_dinvs[NG][NN];      // |.|=dinv, sign set = node is_center
__device__ float g_selfn[NG][NN];
__device__ float g_sv[NG][NN];
__device__ float g_svd[NG][NN];        // sv * dinv (0 for out-of-sub)
__device__ unsigned long long g_packed[NG];
__device__ float g_seq[TS * HD];
__device__ float g_gi[TS][3 * HD];     // precomputed Wih @ seq[t] + bih
__device__ unsigned long long g_bar[NG * 16];   // one line per group
__device__ unsigned long long g_done;

__global__ void k_pre() {
    int i = threadIdx.x;
    if (i < NG * 16) g_bar[i] = 0ull;
    if (i == 0) g_done = 0ull;
}

// group-local grid barrier (gpb blocks per group)
__device__ __forceinline__ void gbar(int grp, unsigned long long target) {
    __syncthreads();
    if (threadIdx.x == 0) {
        __threadfence();
        atomicAdd(&g_bar[grp * 16], 1ull);
        while (*((volatile unsigned long long*)&g_bar[grp * 16]) < target)
            __nanosleep(64);
        __threadfence();
    }
    __syncthreads();
}

// warp-collective: build node v's 68-float normalized feature row from ELL.
// float2 x loads: one warp-wide LDG.64 covers a full 64-col row.
__device__ __forceinline__ void gather_row(const float2* __restrict__ xt2,
                                           int grp, int v,
                                           float* dst, int lane) {
    float dv = g_dinvs[grp][v];
    float di = fabsf(dv);
    int c = g_cnt[grp][v]; if (c > EC) c = EC;
    const int* row = &g_ell[grp][v * EC];
    float ax = 0.f, ay = 0.f, wc = 0.f, wo = 0.f;
    for (int base = 0; base < c; base += 32) {
        int sl = 0; float ds = 0.f;
        if (base + lane < c) {
            sl = row[base + lane];
            ds = g_dinvs[grp][sl];
        }
        float wl = fabsf(ds) * di;
        if (ds < 0.f) wc += wl; else wo += wl;
        int nn2 = c - base; if (nn2 > 32) nn2 = 32;
        #pragma unroll 8
        for (int e2 = 0; e2 < nn2; e2++) {
            float w = __shfl_sync(~0u, wl, e2);
            if (w != 0.f) {
                int s2 = __shfl_sync(~0u, sl, e2);
                float2 xv = xt2[s2 * (FD / 2) + lane];
                ax += xv.x * w;
                ay += xv.y * w;
            }
        }
    }
    float sn = g_selfn[grp][v];
    float2 xs = xt2[v * (FD / 2) + lane];
    ax += xs.x * sn;
    ay += xs.y * sn;
    dst[2 * lane]     = ax;
    dst[2 * lane + 1] = ay;
    #pragma unroll
    for (int off2 = 16; off2; off2 >>= 1) {
        wc += __shfl_down_sync(~0u, wc, off2);
        wo += __shfl_down_sync(~0u, wo, off2);
    }
    if (lane == 0) {
        int ic = (dv < 0.f);
        dst[64] = wc + (ic ? sn : 0.f);
        dst[65] = wo + (ic ? 0.f : sn);
        dst[66] = 0.f;
        dst[67] = 0.f;
    }
}

// ---------------- the megakernel ---------------------------------------------

__global__ void __launch_bounds__(256, 5) k_mega(
    const float* __restrict__ x, const int* __restrict__ ei,
    const int* __restrict__ tgt,
    const float* __restrict__ W1, const float* __restrict__ b1,
    const float* __restrict__ W2, const float* __restrict__ b2,
    const float* __restrict__ Wih, const float* __restrict__ Whh,
    const float* __restrict__ bih, const float* __restrict__ bhh,
    const float* __restrict__ Wc1, const float* __restrict__ bc1,
    const float* __restrict__ Wc2, const float* __restrict__ bc2,
    float* __restrict__ out)
{
    const int tid = threadIdx.x, B = blockIdx.x, G = gridDim.x;
    const int gpb = G / NG;
    const int lane = tid & 31, wid = tid >> 5;
    const int tcol = tid & 127, half = tid >> 7;

    __shared__ float s_W1[KP * HD];      // 34816 B (row 67 zeroed)
    __shared__ float szrow[8][KP];       // rows 272 B -> 16B-aligned
    __shared__ int   sact[8];
    __shared__ float sred[8][4];
    __shared__ int   s_tgt[CT];
    __shared__ int   s_top, s_m;
    __shared__ int   s_list[LM];
    __shared__ float s_wl[LM];
    __shared__ float s_z2[HD];
    __shared__ float s_sq[HD];
    __shared__ float s_h[HD];
    __shared__ float s_gh[3 * HD];
    __shared__ float s_hid[HD / 2];

    // cooperative W1 load (padded row 67 = 0)
    for (int k = tid; k < KP * HD; k += 256)
        s_W1[k] = (k < KD * HD) ? W1[k] : 0.f;

    if (B < NG * gpb) {
        const int grp = B / gpb;
        const int gb  = B % gpb;
        unsigned long long barn = 0;

        const float w2c = W2[tcol * HD + (HD - 1)];
        const float bb  = b1[tcol];

        const int t0 = grp;
        const float*  xt  = x + (size_t)t0 * NN * FD;
        const float2* xt2 = (const float2*)xt;
        const int*    eit = ei + (size_t)t0 * 2 * NE;

        // ---- P0: membership init (flags/isc/cnt/packed) ----
        for (int j = tid; j < CT; j += 256) s_tgt[j] = tgt[t0 * CT + j];
        __syncthreads();
        for (int i = gb * 256 + tid; i < NN; i += gpb * 256) {
            int m = 0;
            #pragma unroll 8
            for (int j = 0; j < CT; j++) m |= (s_tgt[j] == i);
            g_flagA[grp][i] = m;
            g_flagB[grp][i] = m;
            g_isc[grp][i]   = m;
            g_cnt[grp][i]   = 0;
        }
        if (gb == 0 && tid == 0) g_packed[grp] = 0ull;
        gbar(grp, ++barn * (unsigned long long)gpb);

        // ---- P1: hop 1 (A->B) + ELL fill, 4 edges/iter for MLP ----
        {
            const int4* src4 = (const int4*)eit;
            const int4* dst4 = (const int4*)(eit + NE);
            for (int e4 = gb * 256 + tid; e4 < NE / 4; e4 += gpb * 256) {
                int4 s4 = src4[e4];
                int4 d4 = dst4[e4];
                int sl0 = atomicAdd(&g_cnt[grp][d4.x], 1);
                int sl1 = atomicAdd(&g_cnt[grp][d4.y], 1);
                int sl2 = atomicAdd(&g_cnt[grp][d4.z], 1);
                int sl3 = atomicAdd(&g_cnt[grp][d4.w], 1);
                if (sl0 < EC) g_ell[grp][d4.x * EC + sl0] = s4.x;
                if (sl1 < EC) g_ell[grp][d4.y * EC + sl1] = s4.y;
                if (sl2 < EC) g_ell[grp][d4.z * EC + sl2] = s4.z;
                if (sl3 < EC) g_ell[grp][d4.w * EC + sl3] = s4.w;
                int fs0 = g_flagA[grp][s4.x], fd0 = g_flagA[grp][d4.x];
                int fs1 = g_flagA[grp][s4.y], fd1 = g_flagA[grp][d4.y];
                int fs2 = g_flagA[grp][s4.z], fd2 = g_flagA[grp][d4.z];
                int fs3 = g_flagA[grp][s4.w], fd3 = g_flagA[grp][d4.w];
                if (fs0) g_flagB[grp][d4.x] = 1;
                if (fd0) g_flagB[grp][s4.x] = 1;
                if (fs1) g_flagB[grp][d4.y] = 1;
                if (fd1) g_flagB[grp][s4.y] = 1;
                if (fs2) g_flagB[grp][d4.z] = 1;
                if (fd2) g_flagB[grp][s4.z] = 1;
                if (fs3) g_flagB[grp][d4.w] = 1;
                if (fd3) g_flagB[grp][s4.w] = 1;
            }
        }
        gbar(grp, ++barn * gpb);

        // ---- P2: hop 2 (B->A), 4 edges/iter ----
        {
            const int4* src4 = (const int4*)eit;
            const int4* dst4 = (const int4*)(eit + NE);
            for (int e4 = gb * 256 + tid; e4 < NE / 4; e4 += gpb * 256) {
                int4 s4 = src4[e4];
                int4 d4 = dst4[e4];
                int fs0 = g_flagB[grp][s4.x], fd0 = g_flagB[grp][d4.x];
                int fs1 = g_flagB[grp][s4.y], fd1 = g_flagB[grp][d4.y];
                int fs2 = g_flagB[grp][s4.z], fd2 = g_flagB[grp][d4.z];
                int fs3 = g_flagB[grp][s4.w], fd3 = g_flagB[grp][d4.w];
                if (fs0) g_flagA[grp][d4.x] = 1;
                if (fd0) g_flagA[grp][s4.x] = 1;
                if (fs1) g_flagA[grp][d4.y] = 1;
                if (fd1) g_flagA[grp][s4.y] = 1;
                if (fs2) g_flagA[grp][d4.z] = 1;
                if (fd2) g_flagA[grp][s4.z] = 1;
                if (fs3) g_flagA[grp][d4.w] = 1;
                if (fd3) g_flagA[grp][s4.w] = 1;
            }
        }
        gbar(grp, ++barn * gpb);

        // ---- P3: deg -> dinv (sign-packed with is_center) + selfn ----
        for (int i = gb * 8 + wid; i < NN; i += gpb * 8) {
            if (!g_flagA[grp][i]) {
                if (lane == 0) { g_dinvs[grp][i] = 0.f; g_selfn[grp][i] = 0.f; }
                continue;
            }
            int c = g_cnt[grp][i]; if (c > EC) c = EC;
            const int* row = &g_ell[grp][i * EC];
            int deg = 0;
            for (int e = lane; e < c; e += 32)
                deg += g_flagA[grp][row[e]];
            #pragma unroll
            for (int o2 = 16; o2; o2 >>= 1)
                deg += __shfl_down_sync(~0u, deg, o2);
            if (lane == 0) {
                float di = rsqrtf((float)deg + 1.0f);
                g_dinvs[grp][i] = g_isc[grp][i] ? -di : di;
                g_selfn[grp][i] = di * di;
            }
        }
        gbar(grp, ++barn * gpb);

        // ---- P4: gather + W1 GEMM (float4 z reads + shmem W1) + sv ----
        for (int i0 = gb * 8; i0 < NN; i0 += gpb * 8) {
            int i = i0 + wid;
            int active = 0;
            if (i < NN && g_dinvs[grp][i] != 0.f) {
                active = 1;
                gather_row(xt2, grp, i, szrow[wid], lane);
            }
            if (lane == 0) sact[wid] = active;
            __syncthreads();

            float acc0 = bb, acc1 = bb, acc2 = bb, acc3 = bb;
            const int h4 = half * 4;
            #pragma unroll 1
            for (int k = 0; k < KP; k += 4) {
                float4 z0 = *(const float4*)&szrow[h4 + 0][k];
                float4 z1 = *(const float4*)&szrow[h4 + 1][k];
                float4 z2 = *(const float4*)&szrow[h4 + 2][k];
                float4 z3 = *(const float4*)&szrow[h4 + 3][k];
                float wa  = s_W1[(k + 0) * HD + tcol];
                float wb  = s_W1[(k + 1) * HD + tcol];
                float wcv = s_W1[(k + 2) * HD + tcol];
                float wd  = s_W1[(k + 3) * HD + tcol];
                acc0 += z0.x * wa + z0.y * wb + z0.z * wcv + z0.w * wd;
                acc1 += z1.x * wa + z1.y * wb + z1.z * wcv + z1.w * wd;
                acc2 += z2.x * wa + z2.y * wb + z2.z * wcv + z2.w * wd;
                acc3 += z3.x * wa + z3.y * wb + z3.z * wcv + z3.w * wd;
            }
            float pv[4];
            pv[0] = sact[h4 + 0] ? fmaxf(acc0, 0.f) * w2c : 0.f;
            pv[1] = sact[h4 + 1] ? fmaxf(acc1, 0.f) * w2c : 0.f;
            pv[2] = sact[h4 + 2] ? fmaxf(acc2, 0.f) * w2c : 0.f;
            pv[3] = sact[h4 + 3] ? fmaxf(acc3, 0.f) * w2c : 0.f;
            #pragma unroll
            for (int r = 0; r < 4; r++) {
                float p = pv[r];
                #pragma unroll
                for (int o2 = 16; o2; o2 >>= 1)
                    p += __shfl_down_sync(~0u, p, o2);
                if (lane == 0) sred[wid][r] = p;
            }
            __syncthreads();
            if (tid < 8 && (i0 + tid) < NN) {
                if (sact[tid]) {
                    int h2 = tid >> 2, rl = tid & 3;
                    float sv = sred[h2 * 4 + 0][rl] + sred[h2 * 4 + 1][rl]
                             + sred[h2 * 4 + 2][rl] + sred[h2 * 4 + 3][rl];
                    g_sv[grp][i0 + tid]  = sv;
                    g_svd[grp][i0 + tid] = sv * fabsf(g_dinvs[grp][i0 + tid]);
                } else {
                    g_svd[grp][i0 + tid] = 0.f;
                }
            }
            __syncthreads();
        }
        gbar(grp, ++barn * gpb);

        // ---- P5: scalar layer-2 gather + argmax ----
        {
            const float b2h = b2[HD - 1];
            for (int i = gb * 8 + wid; i < NN; i += gpb * 8) {
                if (!g_flagA[grp][i]) continue;
                int c = g_cnt[grp][i]; if (c > EC) c = EC;
                const int* row = &g_ell[grp][i * EC];
                float acc = 0.f;
                for (int e = lane; e < c; e += 32)
                    acc += g_svd[grp][row[e]];
                #pragma unroll
                for (int o2 = 16; o2; o2 >>= 1)
                    acc += __shfl_down_sync(~0u, acc, o2);
                if (lane == 0) {
                    float v = acc * fabsf(g_dinvs[grp][i])
                            + g_sv[grp][i] * g_selfn[grp][i] + b2h;
                    v = fmaxf(v, 0.f);   // >=0: bits monotone as unsigned
                    unsigned long long key =
                        ((unsigned long long)__float_as_uint(v) << 32) |
                        (unsigned long long)(0xFFFFFFFFu - (unsigned)i);
                    atomicMax(&g_packed[grp], key);
                }
            }
        }
        gbar(grp, ++barn * gpb);

        // ---- P6 (gb 0): top-node layer2 recompute + seq + gi ----
        if (gb == 0) {
            if (tid == 0) {
                s_top = (int)(0xFFFFFFFFu -
                              (unsigned)(g_packed[grp] & 0xFFFFFFFFull));
                s_m = 0;
            }
            __syncthreads();
            int top = s_top;
            float dtop = fabsf(g_dinvs[grp][top]);
            int ctp = g_cnt[grp][top]; if (ctp > EC) ctp = EC;
            const int* rowT = &g_ell[grp][top * EC];
            for (int e = tid; e < ctp; e += 256) {
                int s = rowT[e];
                float w = fabsf(g_dinvs[grp][s]) * dtop;
                if (w != 0.f) {
                    int p = atomicAdd(&s_m, 1);
                    if (p < LM - 1) { s_list[p] = s; s_wl[p] = w; }
                }
            }
            __syncthreads();
            if (tid == 0) {
                int p = s_m; if (p > LM - 1) p = LM - 1;
                s_list[p] = top; s_wl[p] = g_selfn[grp][top];
                s_m = p + 1;
            }
            __syncthreads();
            int m = s_m;
            float z2acc = 0.f;
            for (int b0 = 0; b0 < m; b0 += 8) {
                int r = b0 + wid;
                if (r < m) gather_row(xt2, grp, s_list[r], szrow[wid], lane);
                __syncthreads();
                float acc0 = bb, acc1 = bb, acc2 = bb, acc3 = bb;
                const int h4 = half * 4;
                #pragma unroll 1
                for (int k = 0; k < KP; k += 4) {
                    float4 z0 = *(const float4*)&szrow[h4 + 0][k];
                    float4 z1 = *(const float4*)&szrow[h4 + 1][k];
                    float4 z2 = *(const float4*)&szrow[h4 + 2][k];
                    float4 z3 = *(const float4*)&szrow[h4 + 3][k];
                    float wa  = s_W1[(k + 0) * HD + tcol];
                    float wb  = s_W1[(k + 1) * HD + tcol];
                    float wcv = s_W1[(k + 2) * HD + tcol];
                    float wd  = s_W1[(k + 3) * HD + tcol];
                    acc0 += z0.x * wa + z0.y * wb + z0.z * wcv + z0.w * wd;
                    acc1 += z1.x * wa + z1.y * wb + z1.z * wcv + z1.w * wd;
                    acc2 += z2.x * wa + z2.y * wb + z2.z * wcv + z2.w * wd;
                    acc3 += z3.x * wa + z3.y * wb + z3.z * wcv + z3.w * wd;
                }
                float av[4] = {acc0, acc1, acc2, acc3};
                #pragma unroll
                for (int rr = 0; rr < 4; rr++) {
                    int gidx = b0 + h4 + rr;
                    if (gidx < m)
                        z2acc += fmaxf(av[rr], 0.f) * s_wl[gidx];
                }
                __syncthreads();
            }
            if (half == 1) s_z2[tcol] = z2acc;
            __syncthreads();
            if (half == 0) s_z2[tcol] = z2acc + s_z2[tcol];
            __syncthreads();
            if (tid < HD) {
                float a = b2[tid];
                #pragma unroll 8
                for (int k = 0; k < HD; k++) a += s_z2[k] * W2[k * HD + tid];
                float sq = fmaxf(a, 0.f);
                g_seq[t0 * HD + tid] = sq;
                s_sq[tid] = sq;
            }
            __syncthreads();
            for (int j = wid; j < 3 * HD; j += 8) {
                float dotv = 0.f;
                for (int k = lane; k < HD; k += 32)
                    dotv += Wih[j * HD + k] * s_sq[k];
                #pragma unroll
                for (int o2 = 16; o2; o2 >>= 1)
                    dotv += __shfl_down_sync(~0u, dotv, o2);
                if (lane == 0) g_gi[t0][j] = dotv + bih[j];
            }
        }
    }

    // ---- final: all blocks arrive; block 0 runs GRU + head ----
    if (B != 0) {
        __syncthreads();
        if (tid == 0) { __threadfence(); atomicAdd(&g_done, 1ull); }
        return;
    }
    if (tid == 0) {
        while (*((volatile unsigned long long*)&g_done) <
               (unsigned long long)(G - 1))
            __nanosleep(128);
        __threadfence();
    }
    __syncthreads();

    if (tid < HD) s_h[tid] = 0.f;
    __syncthreads();
    for (int t = 0; t < TS; t++) {
        for (int j = wid; j < 3 * HD; j += 8) {
            float dotv = 0.f;
            for (int k = lane; k < HD; k += 32)
                dotv += Whh[j * HD + k] * s_h[k];
            #pragma unroll
            for (int o2 = 16; o2; o2 >>= 1)
                dotv += __shfl_down_sync(~0u, dotv, o2);
            if (lane == 0) s_gh[j] = dotv + bhh[j];
        }
        __syncthreads();
        if (tid < HD) {
            float r  = 1.f / (1.f + expf(-(g_gi[t][tid] + s_gh[tid])));
            float z  = 1.f / (1.f + expf(-(g_gi[t][HD + tid] + s_gh[HD + tid])));
            float n2 = tanhf(g_gi[t][2 * HD + tid] + r * s_gh[2 * HD + tid]);
            s_h[tid] = (1.f - z) * n2 + z * s_h[tid];
        }
        __syncthreads();
    }
    if (tid < HD / 2) {
        float a = bc1[tid];
        #pragma unroll 8
        for (int k = 0; k < HD; k++) a += s_h[k] * Wc1[k * (HD / 2) + tid];
        s_hid[tid] = fmaxf(a, 0.f);
    }
    __syncthreads();
    if (tid == 0) {
        float a = bc2[0];
        for (int m2 = 0; m2 < HD / 2; m2++) a += s_hid[m2] * Wc2[m2];
        out[0] = 1.f / (1.f + expf(-a));
    }
}

// ---------------- launch -----------------------------------------------------

extern "C" void kernel_launch(void* const* d_in, const int* in_sizes, int n_in,
                              void* d_out, int out_size) {
    const float* x   = (const float*)d_in[0];
    const int*   ei  = (const int*)  d_in[1];
    const int*   tgt = (const int*)  d_in[2];
    const float* W1  = (const float*)d_in[3];
    const float* b1  = (const float*)d_in[4];
    const float* W2  = (const float*)d_in[5];
    const float* b2  = (const float*)d_in[6];
    const float* Wih = (const float*)d_in[7];
    const float* Whh = (const float*)d_in[8];
    const float* bih = (const float*)d_in[9];
    const float* bhh = (const float*)d_in[10];
    const float* Wc1 = (const float*)d_in[11];
    const float* bc1 = (const float*)d_in[12];
    const float* Wc2 = (const float*)d_in[13];
    const float* bc2 = (const float*)d_in[14];
    float* out = (float*)d_out;

    int dev = 0;
    cudaGetDevice(&dev);
    int nsm = 0;
    cudaDeviceGetAttribute(&nsm, cudaDevAttrMultiProcessorCount, dev);
    int perSM = 0;
    cudaOccupancyMaxActiveBlocksPerMultiprocessor(&perSM, k_mega, 256, 0);
    if (perSM < 1) perSM = 1;
    int G = nsm * perSM;
    if (G < NG) G = NG;
    if (G > NG * 256) G = NG * 256;

    k_pre<<<1, 128>>>();
    k_mega<<<G, 256>>>(x, ei, tgt, W1, b1, W2, b2,
                       Wih, Whh, bih, bhh, Wc1, bc1, Wc2, bc2, out);
}

// round 13
// speedup vs baseline: 1.0385x; 1.0385x over previous
#include <cuda_runtime.h>

#define NN 20000
#define NE 400000
#define FD 64
#define CT 64
#define HD 128
#define TS 6
#define KD 67      // F + 3 label channels
#define KP 68      // padded to multiple of 4
#define NG 6       // concurrent snapshot groups
#define EC 64      // ELL row capacity (in-degree ~ Poisson(20); P(>64) ~ 1e-20)
#define LM 256     // top-node neighbor list cap

// ---------------- scratch (static device globals; no allocation) -------------
__device__ int   g_flagA[NG][NN];
__device__ int   g_flagB[NG][NN];
__device__ int   g_isc[NG][NN];
__device__ int   g_cnt[NG][NN];
__device__ int   g_ell[NG][NN * EC];   // ELL src lists (row i at i*EC)
__device__ float g_dinvs[NG][NN];      // |.|=dinv, sign set = node is_center
__device__ float g_selfn[NG][NN];
__device__ float g_sv[NG][NN];
__device__ float g_svd[NG][NN];        // sv * dinv (0 for out-of-sub)
__device__ unsigned long long g_packed[NG];
__device__ float g_seq[TS * HD];
__device__ float g_gi[TS][3 * HD];     // precomputed Wih @ seq[t] + bih
__device__ unsigned long long g_bar[NG * 16];   // one line per group
__device__ unsigned long long g_done;

__global__ void k_pre() {
    int i = threadIdx.x;
    if (i < NG * 16) g_bar[i] = 0ull;
    if (i == 0) g_done = 0ull;
}

// group-local grid barrier (gpb blocks per group)
__device__ __forceinline__ void gbar(int grp, unsigned long long target) {
    __syncthreads();
    if (threadIdx.x == 0) {
        __threadfence();
        atomicAdd(&g_bar[grp * 16], 1ull);
        while (*((volatile unsigned long long*)&g_bar[grp * 16]) < target)
            __nanosleep(64);
        __threadfence();
    }
    __syncthreads();
}

// warp-collective: build node v's 68-float normalized feature row from ELL.
// float2 x loads: one warp-wide LDG.64 covers a full 64-col row.
// (identical to the 787us-proven version)
__device__ __forceinline__ void gather_row(const float2* __restrict__ xt2,
                                           int grp, int v,
                                           float* dst, int lane) {
    float dv = g_dinvs[grp][v];
    float di = fabsf(dv);
    int c = g_cnt[grp][v]; if (c > EC) c = EC;
    const int* row = &g_ell[grp][v * EC];
    float ax = 0.f, ay = 0.f, wc = 0.f, wo = 0.f;
    for (int base = 0; base < c; base += 32) {
        int sl = 0; float ds = 0.f;
        if (base + lane < c) {
            sl = row[base + lane];
            ds = g_dinvs[grp][sl];
        }
        float wl = fabsf(ds) * di;
        if (ds < 0.f) wc += wl; else wo += wl;
        int nn2 = c - base; if (nn2 > 32) nn2 = 32;
        #pragma unroll 4
        for (int e2 = 0; e2 < nn2; e2++) {
            float w = __shfl_sync(~0u, wl, e2);
            if (w != 0.f) {
                int s2 = __shfl_sync(~0u, sl, e2);
                float2 xv = xt2[s2 * (FD / 2) + lane];
                ax += xv.x * w;
                ay += xv.y * w;
            }
        }
    }
    float sn = g_selfn[grp][v];
    float2 xs = xt2[v * (FD / 2) + lane];
    ax += xs.x * sn;
    ay += xs.y * sn;
    dst[2 * lane]     = ax;
    dst[2 * lane + 1] = ay;
    #pragma unroll
    for (int off2 = 16; off2; off2 >>= 1) {
        wc += __shfl_down_sync(~0u, wc, off2);
        wo += __shfl_down_sync(~0u, wo, off2);
    }
    if (lane == 0) {
        int ic = (dv < 0.f);
        dst[64] = wc + (ic ? sn : 0.f);
        dst[65] = wo + (ic ? 0.f : sn);
        dst[66] = 0.f;
        dst[67] = 0.f;
    }
}

// ---------------- the megakernel ---------------------------------------------

__global__ void __launch_bounds__(256, 4) k_mega(
    const float* __restrict__ x, const int* __restrict__ ei,
    const int* __restrict__ tgt,
    const float* __restrict__ W1, const float* __restrict__ b1,
    const float* __restrict__ W2, const float* __restrict__ b2,
    const float* __restrict__ Wih, const float* __restrict__ Whh,
    const float* __restrict__ bih, const float* __restrict__ bhh,
    const float* __restrict__ Wc1, const float* __restrict__ bc1,
    const float* __restrict__ Wc2, const float* __restrict__ bc2,
    float* __restrict__ out)
{
    const int tid = threadIdx.x, B = blockIdx.x, G = gridDim.x;
    const int gpb = G / NG;
    const int lane = tid & 31, wid = tid >> 5;
    const int tcol = tid & 127, half = tid >> 7;

    __shared__ float s_W1[KP * HD];      // 34816 B (row 67 zeroed)
    __shared__ float szrow[8][KP];       // rows 272 B -> 16B-aligned
    __shared__ int   sact[8];
    __shared__ float sred[8][4];
    __shared__ int   s_tgt[CT];
    __shared__ int   s_top, s_m;
    __shared__ int   s_list[LM];
    __shared__ float s_wl[LM];
    __shared__ float s_z2[HD];
    __shared__ float s_sq[HD];
    __shared__ float s_h[HD];
    __shared__ float s_gh[3 * HD];
    __shared__ float s_hid[HD / 2];

    // cooperative W1 load (padded row 67 = 0)
    for (int k = tid; k < KP * HD; k += 256)
        s_W1[k] = (k < KD * HD) ? W1[k] : 0.f;

    if (B < NG * gpb) {
        const int grp = B / gpb;
        const int gb  = B % gpb;
        unsigned long long barn = 0;

        const float w2c = W2[tcol * HD + (HD - 1)];
        const float bb  = b1[tcol];

        const int t0 = grp;
        const float*  xt  = x + (size_t)t0 * NN * FD;
        const float2* xt2 = (const float2*)xt;
        const int*    eit = ei + (size_t)t0 * 2 * NE;

        // ---- P0: membership init (flags/isc/cnt/packed) ----
        for (int j = tid; j < CT; j += 256) s_tgt[j] = tgt[t0 * CT + j];
        __syncthreads();
        for (int i = gb * 256 + tid; i < NN; i += gpb * 256) {
            int m = 0;
            #pragma unroll 8
            for (int j = 0; j < CT; j++) m |= (s_tgt[j] == i);
            g_flagA[grp][i] = m;
            g_flagB[grp][i] = m;
            g_isc[grp][i]   = m;
            g_cnt[grp][i]   = 0;
        }
        if (gb == 0 && tid == 0) g_packed[grp] = 0ull;
        gbar(grp, ++barn * (unsigned long long)gpb);

        // ---- P1: hop 1 (A->B) + ELL fill, 4 edges/iter for MLP ----
        {
            const int4* src4 = (const int4*)eit;
            const int4* dst4 = (const int4*)(eit + NE);
            for (int e4 = gb * 256 + tid; e4 < NE / 4; e4 += gpb * 256) {
                int4 s4 = src4[e4];
                int4 d4 = dst4[e4];
                int sl0 = atomicAdd(&g_cnt[grp][d4.x], 1);
                int sl1 = atomicAdd(&g_cnt[grp][d4.y], 1);
                int sl2 = atomicAdd(&g_cnt[grp][d4.z], 1);
                int sl3 = atomicAdd(&g_cnt[grp][d4.w], 1);
                if (sl0 < EC) g_ell[grp][d4.x * EC + sl0] = s4.x;
                if (sl1 < EC) g_ell[grp][d4.y * EC + sl1] = s4.y;
                if (sl2 < EC) g_ell[grp][d4.z * EC + sl2] = s4.z;
                if (sl3 < EC) g_ell[grp][d4.w * EC + sl3] = s4.w;
                int fs0 = g_flagA[grp][s4.x], fd0 = g_flagA[grp][d4.x];
                int fs1 = g_flagA[grp][s4.y], fd1 = g_flagA[grp][d4.y];
                int fs2 = g_flagA[grp][s4.z], fd2 = g_flagA[grp][d4.z];
                int fs3 = g_flagA[grp][s4.w], fd3 = g_flagA[grp][d4.w];
                if (fs0) g_flagB[grp][d4.x] = 1;
                if (fd0) g_flagB[grp][s4.x] = 1;
                if (fs1) g_flagB[grp][d4.y] = 1;
                if (fd1) g_flagB[grp][s4.y] = 1;
                if (fs2) g_flagB[grp][d4.z] = 1;
                if (fd2) g_flagB[grp][s4.z] = 1;
                if (fs3) g_flagB[grp][d4.w] = 1;
                if (fd3) g_flagB[grp][s4.w] = 1;
            }
        }
        gbar(grp, ++barn * gpb);

        // ---- P2: hop 2 (B->A), 4 edges/iter ----
        {
            const int4* src4 = (const int4*)eit;
            const int4* dst4 = (const int4*)(eit + NE);
            for (int e4 = gb * 256 + tid; e4 < NE / 4; e4 += gpb * 256) {
                int4 s4 = src4[e4];
                int4 d4 = dst4[e4];
                int fs0 = g_flagB[grp][s4.x], fd0 = g_flagB[grp][d4.x];
                int fs1 = g_flagB[grp][s4.y], fd1 = g_flagB[grp][d4.y];
                int fs2 = g_flagB[grp][s4.z], fd2 = g_flagB[grp][d4.z];
                int fs3 = g_flagB[grp][s4.w], fd3 = g_flagB[grp][d4.w];
                if (fs0) g_flagA[grp][d4.x] = 1;
                if (fd0) g_flagA[grp][s4.x] = 1;
                if (fs1) g_flagA[grp][d4.y] = 1;
                if (fd1) g_flagA[grp][s4.y] = 1;
                if (fs2) g_flagA[grp][d4.z] = 1;
                if (fd2) g_flagA[grp][s4.z] = 1;
                if (fs3) g_flagA[grp][d4.w] = 1;
                if (fd3) g_flagA[grp][s4.w] = 1;
            }
        }
        gbar(grp, ++barn * gpb);

        // ---- P3: deg -> dinv (sign-packed with is_center) + selfn ----
        for (int i = gb * 8 + wid; i < NN; i += gpb * 8) {
            if (!g_flagA[grp][i]) {
                if (lane == 0) { g_dinvs[grp][i] = 0.f; g_selfn[grp][i] = 0.f; }
                continue;
            }
            int c = g_cnt[grp][i]; if (c > EC) c = EC;
            const int* row = &g_ell[grp][i * EC];
            int deg = 0;
            for (int e = lane; e < c; e += 32)
                deg += g_flagA[grp][row[e]];
            #pragma unroll
            for (int o2 = 16; o2; o2 >>= 1)
                deg += __shfl_down_sync(~0u, deg, o2);
            if (lane == 0) {
                float di = rsqrtf((float)deg + 1.0f);
                g_dinvs[grp][i] = g_isc[grp][i] ? -di : di;
                g_selfn[grp][i] = di * di;
            }
        }
        gbar(grp, ++barn * gpb);

        // ---- P4: gather + W1 GEMM (float4 z reads + shmem W1) + sv ----
        for (int i0 = gb * 8; i0 < NN; i0 += gpb * 8) {
            int i = i0 + wid;
            int active = 0;
            if (i < NN && g_dinvs[grp][i] != 0.f) {
                active = 1;
                gather_row(xt2, grp, i, szrow[wid], lane);
            }
            if (lane == 0) sact[wid] = active;
            __syncthreads();

            float acc0 = bb, acc1 = bb, acc2 = bb, acc3 = bb;
            const int h4 = half * 4;
            #pragma unroll 1
            for (int k = 0; k < KP; k += 4) {
                float4 z0 = *(const float4*)&szrow[h4 + 0][k];
                float4 z1 = *(const float4*)&szrow[h4 + 1][k];
                float4 z2 = *(const float4*)&szrow[h4 + 2][k];
                float4 z3 = *(const float4*)&szrow[h4 + 3][k];
                float wa  = s_W1[(k + 0) * HD + tcol];
                float wb  = s_W1[(k + 1) * HD + tcol];
                float wcv = s_W1[(k + 2) * HD + tcol];
                float wd  = s_W1[(k + 3) * HD + tcol];
                acc0 += z0.x * wa + z0.y * wb + z0.z * wcv + z0.w * wd;
                acc1 += z1.x * wa + z1.y * wb + z1.z * wcv + z1.w * wd;
                acc2 += z2.x * wa + z2.y * wb + z2.z * wcv + z2.w * wd;
                acc3 += z3.x * wa + z3.y * wb + z3.z * wcv + z3.w * wd;
            }
            float pv[4];
            pv[0] = sact[h4 + 0] ? fmaxf(acc0, 0.f) * w2c : 0.f;
            pv[1] = sact[h4 + 1] ? fmaxf(acc1, 0.f) * w2c : 0.f;
            pv[2] = sact[h4 + 2] ? fmaxf(acc2, 0.f) * w2c : 0.f;
            pv[3] = sact[h4 + 3] ? fmaxf(acc3, 0.f) * w2c : 0.f;
            #pragma unroll
            for (int r = 0; r < 4; r++) {
                float p = pv[r];
                #pragma unroll
                for (int o2 = 16; o2; o2 >>= 1)
                    p += __shfl_down_sync(~0u, p, o2);
                if (lane == 0) sred[wid][r] = p;
            }
            __syncthreads();
            if (tid < 8 && (i0 + tid) < NN) {
                if (sact[tid]) {
                    int h2 = tid >> 2, rl = tid & 3;
                    float sv = sred[h2 * 4 + 0][rl] + sred[h2 * 4 + 1][rl]
                             + sred[h2 * 4 + 2][rl] + sred[h2 * 4 + 3][rl];
                    g_sv[grp][i0 + tid]  = sv;
                    g_svd[grp][i0 + tid] = sv * fabsf(g_dinvs[grp][i0 + tid]);
                } else {
                    g_svd[grp][i0 + tid] = 0.f;
                }
            }
            __syncthreads();
        }
        gbar(grp, ++barn * gpb);

        // ---- P5: scalar layer-2 gather + argmax ----
        {
            const float b2h = b2[HD - 1];
            for (int i = gb * 8 + wid; i < NN; i += gpb * 8) {
                if (!g_flagA[grp][i]) continue;
                int c = g_cnt[grp][i]; if (c > EC) c = EC;
                const int* row = &g_ell[grp][i * EC];
                float acc = 0.f;
                for (int e = lane; e < c; e += 32)
                    acc += g_svd[grp][row[e]];
                #pragma unroll
                for (int o2 = 16; o2; o2 >>= 1)
                    acc += __shfl_down_sync(~0u, acc, o2);
                if (lane == 0) {
                    float v = acc * fabsf(g_dinvs[grp][i])
                            + g_sv[grp][i] * g_selfn[grp][i] + b2h;
                    v = fmaxf(v, 0.f);   // >=0: bits monotone as unsigned
                    unsigned long long key =
                        ((unsigned long long)__float_as_uint(v) << 32) |
                        (unsigned long long)(0xFFFFFFFFu - (unsigned)i);
                    atomicMax(&g_packed[grp], key);
                }
            }
        }
        gbar(grp, ++barn * gpb);

        // ---- P6 (gb 0): top-node layer2 recompute + seq + gi ----
        if (gb == 0) {
            if (tid == 0) {
                s_top = (int)(0xFFFFFFFFu -
                              (unsigned)(g_packed[grp] & 0xFFFFFFFFull));
                s_m = 0;
            }
            __syncthreads();
            int top = s_top;
            float dtop = fabsf(g_dinvs[grp][top]);
            int ctp = g_cnt[grp][top]; if (ctp > EC) ctp = EC;
            const int* rowT = &g_ell[grp][top * EC];
            for (int e = tid; e < ctp; e += 256) {
                int s = rowT[e];
                float w = fabsf(g_dinvs[grp][s]) * dtop;
                if (w != 0.f) {
                    int p = atomicAdd(&s_m, 1);
                    if (p < LM - 1) { s_list[p] = s; s_wl[p] = w; }
                }
            }
            __syncthreads();
            if (tid == 0) {
                int p = s_m; if (p > LM - 1) p = LM - 1;
                s_list[p] = top; s_wl[p] = g_selfn[grp][top];
                s_m = p + 1;
            }
            __syncthreads();
            int m = s_m;
            float z2acc = 0.f;
            for (int b0 = 0; b0 < m; b0 += 8) {
                int r = b0 + wid;
                if (r < m) gather_row(xt2, grp, s_list[r], szrow[wid], lane);
                __syncthreads();
                float acc0 = bb, acc1 = bb, acc2 = bb, acc3 = bb;
                const int h4 = half * 4;
                #pragma unroll 1
                for (int k = 0; k < KP; k += 4) {
                    float4 z0 = *(const float4*)&szrow[h4 + 0][k];
                    float4 z1 = *(const float4*)&szrow[h4 + 1][k];
                    float4 z2 = *(const float4*)&szrow[h4 + 2][k];
                    float4 z3 = *(const float4*)&szrow[h4 + 3][k];
                    float wa  = s_W1[(k + 0) * HD + tcol];
                    float wb  = s_W1[(k + 1) * HD + tcol];
                    float wcv = s_W1[(k + 2) * HD + tcol];
                    float wd  = s_W1[(k + 3) * HD + tcol];
                    acc0 += z0.x * wa + z0.y * wb + z0.z * wcv + z0.w * wd;
                    acc1 += z1.x * wa + z1.y * wb + z1.z * wcv + z1.w * wd;
                    acc2 += z2.x * wa + z2.y * wb + z2.z * wcv + z2.w * wd;
                    acc3 += z3.x * wa + z3.y * wb + z3.z * wcv + z3.w * wd;
                }
                float av[4] = {acc0, acc1, acc2, acc3};
                #pragma unroll
                for (int rr = 0; rr < 4; rr++) {
                    int gidx = b0 + h4 + rr;
                    if (gidx < m)
                        z2acc += fmaxf(av[rr], 0.f) * s_wl[gidx];
                }
                __syncthreads();
            }
            if (half == 1) s_z2[tcol] = z2acc;
            __syncthreads();
            if (half == 0) s_z2[tcol] = z2acc + s_z2[tcol];
            __syncthreads();
            if (tid < HD) {
                float a = b2[tid];
                #pragma unroll 8
                for (int k = 0; k < HD; k++) a += s_z2[k] * W2[k * HD + tid];
                float sq = fmaxf(a, 0.f);
                g_seq[t0 * HD + tid] = sq;
                s_sq[tid] = sq;
            }
            __syncthreads();
            for (int j = wid; j < 3 * HD; j += 8) {
                float dotv = 0.f;
                for (int k = lane; k < HD; k += 32)
                    dotv += Wih[j * HD + k] * s_sq[k];
                #pragma unroll
                for (int o2 = 16; o2; o2 >>= 1)
                    dotv += __shfl_down_sync(~0u, dotv, o2);
                if (lane == 0) g_gi[t0][j] = dotv + bih[j];
            }
        }
    }

    // ---- final: all blocks arrive; block 0 runs GRU + head ----
    if (B != 0) {
        __syncthreads();
        if (tid == 0) { __threadfence(); atomicAdd(&g_done, 1ull); }
        return;
    }
    if (tid == 0) {
        while (*((volatile unsigned long long*)&g_done) <
               (unsigned long long)(G - 1))
            __nanosleep(128);
        __threadfence();
    }
    __syncthreads();

    if (tid < HD) s_h[tid] = 0.f;
    __syncthreads();
    for (int t = 0; t < TS; t++) {
        for (int j = wid; j < 3 * HD; j += 8) {
            float dotv = 0.f;
            for (int k = lane; k < HD; k += 32)
                dotv += Whh[j * HD + k] * s_h[k];
            #pragma unroll
            for (int o2 = 16; o2; o2 >>= 1)
                dotv += __shfl_down_sync(~0u, dotv, o2);
            if (lane == 0) s_gh[j] = dotv + bhh[j];
        }
        __syncthreads();
        if (tid < HD) {
            float r  = 1.f / (1.f + expf(-(g_gi[t][tid] + s_gh[tid])));
            float z  = 1.f / (1.f + expf(-(g_gi[t][HD + tid] + s_gh[HD + tid])));
            float n2 = tanhf(g_gi[t][2 * HD + tid] + r * s_gh[2 * HD + tid]);
            s_h[tid] = (1.f - z) * n2 + z * s_h[tid];
        }
        __syncthreads();
    }
    if (tid < HD / 2) {
        float a = bc1[tid];
        #pragma unroll 8
        for (int k = 0; k < HD; k++) a += s_h[k] * Wc1[k * (HD / 2) + tid];
        s_hid[tid] = fmaxf(a, 0.f);
    }
    __syncthreads();
    if (tid == 0) {
        float a = bc2[0];
        for (int m2 = 0; m2 < HD / 2; m2++) a += s_hid[m2] * Wc2[m2];
        out[0] = 1.f / (1.f + expf(-a));
    }
}

// ---------------- launch -----------------------------------------------------

extern "C" void kernel_launch(void* const* d_in, const int* in_sizes, int n_in,
                              void* d_out, int out_size) {
    const float* x   = (const float*)d_in[0];
    const int*   ei  = (const int*)  d_in[1];
    const int*   tgt = (const int*)  d_in[2];
    const float* W1  = (const float*)d_in[3];
    const float* b1  = (const float*)d_in[4];
    const float* W2  = (const float*)d_in[5];
    const float* b2  = (const float*)d_in[6];
    const float* Wih = (const float*)d_in[7];
    const float* Whh = (const float*)d_in[8];
    const float* bih = (const float*)d_in[9];
    const float* bhh = (const float*)d_in[10];
    const float* Wc1 = (const float*)d_in[11];
    const float* bc1 = (const float*)d_in[12];
    const float* Wc2 = (const float*)d_in[13];
    const float* bc2 = (const float*)d_in[14];
    float* out = (float*)d_out;

    int dev = 0;
    cudaGetDevice(&dev);
    int nsm = 0;
    cudaDeviceGetAttribute(&nsm, cudaDevAttrMultiProcessorCount, dev);
    int perSM = 0;
    cudaOccupancyMaxActiveBlocksPerMultiprocessor(&perSM, k_mega, 256, 0);
    if (perSM < 1) perSM = 1;
    int G = nsm * perSM;
    if (G < NG) G = NG;
    if (G > NG * 256) G = NG * 256;

    k_pre<<<1, 128>>>();
    k_mega<<<G, 256>>>(x, ei, tgt, W1, b1, W2, b2,
                       Wih, Whh, bih, bhh, Wc1, bc1, Wc2, bc2, out);
}

// round 14
// speedup vs baseline: 1.0942x; 1.0537x over previous
#include <cuda_runtime.h>

#define NN 20000
#define NE 400000
#define FD 64
#define CT 64
#define HD 128
#define TS 6
#define KD 67      // F + 3 label channels
#define KP 68      // padded to multiple of 4
#define NG 6       // concurrent snapshot groups
#define EC 64      // ELL row capacity (in-degree ~ Poisson(20); P(>64) ~ 1e-20)
#define LM 256     // top-node neighbor list cap

// ---------------- scratch (static device globals; no allocation) -------------
__device__ int   g_flagA[NG][NN];
__device__ int   g_flagB[NG][NN];
__device__ int   g_isc[NG][NN];
__device__ int   g_cnt[NG][NN];
__device__ int   g_ell[NG][NN * EC];   // ELL src lists (row i at i*EC)
__device__ float g_dinvs[NG][NN];      // |.|=dinv, sign set = node is_center
__device__ float g_selfn[NG][NN];
__device__ float g_sv[NG][NN];
__device__ float g_svd[NG][NN];        // sv * dinv (0 for out-of-sub)
__device__ unsigned long long g_packed[NG];
__device__ float g_seq[TS * HD];
__device__ float g_gi[TS][3 * HD];     // precomputed Wih @ seq[t] + bih
__device__ unsigned long long g_bar[NG * 16];   // one line per group
__device__ unsigned long long g_done;

__global__ void k_pre() {
    int i = threadIdx.x;
    if (i < NG * 16) g_bar[i] = 0ull;
    if (i == 0) g_done = 0ull;
}

// group-local grid barrier (gpb blocks per group)
__device__ __forceinline__ void gbar(int grp, unsigned long long target) {
    __syncthreads();
    if (threadIdx.x == 0) {
        __threadfence();
        atomicAdd(&g_bar[grp * 16], 1ull);
        while (*((volatile unsigned long long*)&g_bar[grp * 16]) < target)
            __nanosleep(64);
        __threadfence();
    }
    __syncthreads();
}

// warp-collective: build node v's 68-float normalized feature row from ELL.
// float2 x loads: one warp-wide LDG.64 covers a full 64-col row.
__device__ __forceinline__ void gather_row(const float2* __restrict__ xt2,
                                           int grp, int v,
                                           float* dst, int lane) {
    float dv = g_dinvs[grp][v];
    float di = fabsf(dv);
    int c = g_cnt[grp][v]; if (c > EC) c = EC;
    const int* row = &g_ell[grp][v * EC];
    float ax = 0.f, ay = 0.f, wc = 0.f, wo = 0.f;
    for (int base = 0; base < c; base += 32) {
        int sl = 0; float ds = 0.f;
        if (base + lane < c) {
            sl = row[base + lane];
            ds = g_dinvs[grp][sl];
        }
        float wl = fabsf(ds) * di;
        if (ds < 0.f) wc += wl; else wo += wl;
        int nn2 = c - base; if (nn2 > 32) nn2 = 32;
        #pragma unroll 4
        for (int e2 = 0; e2 < nn2; e2++) {
            float w = __shfl_sync(~0u, wl, e2);
            if (w != 0.f) {
                int s2 = __shfl_sync(~0u, sl, e2);
                float2 xv = xt2[s2 * (FD / 2) + lane];
                ax += xv.x * w;
                ay += xv.y * w;
            }
        }
    }
    float sn = g_selfn[grp][v];
    float2 xs = xt2[v * (FD / 2) + lane];
    ax += xs.x * sn;
    ay += xs.y * sn;
    dst[2 * lane]     = ax;
    dst[2 * lane + 1] = ay;
    #pragma unroll
    for (int off2 = 16; off2; off2 >>= 1) {
        wc += __shfl_down_sync(~0u, wc, off2);
        wo += __shfl_down_sync(~0u, wo, off2);
    }
    if (lane == 0) {
        int ic = (dv < 0.f);
        dst[64] = wc + (ic ? sn : 0.f);
        dst[65] = wo + (ic ? 0.f : sn);
        dst[66] = 0.f;
        dst[67] = 0.f;
    }
}

// ---------------- the megakernel ---------------------------------------------

__global__ void __launch_bounds__(256, 4) k_mega(
    const float* __restrict__ x, const int* __restrict__ ei,
    const int* __restrict__ tgt,
    const float* __restrict__ W1, const float* __restrict__ b1,
    const float* __restrict__ W2, const float* __restrict__ b2,
    const float* __restrict__ Wih, const float* __restrict__ Whh,
    const float* __restrict__ bih, const float* __restrict__ bhh,
    const float* __restrict__ Wc1, const float* __restrict__ bc1,
    const float* __restrict__ Wc2, const float* __restrict__ bc2,
    float* __restrict__ out)
{
    const int tid = threadIdx.x, B = blockIdx.x, G = gridDim.x;
    const int gpb = G / NG;
    const int lane = tid & 31, wid = tid >> 5;
    const int tcol = tid & 127, half = tid >> 7;

    __shared__ float s_W1[KP * HD];      // 34816 B (row 67 zeroed)
    __shared__ float szrow[8][KP];       // rows 272 B -> 16B-aligned
    __shared__ int   s_tgt[CT];
    __shared__ int   s_top, s_m;
    __shared__ int   s_list[LM];
    __shared__ float s_wl[LM];
    __shared__ float s_z2[HD];
    __shared__ float s_sq[HD];
    __shared__ float s_h[HD];
    __shared__ float s_gh[3 * HD];
    __shared__ float s_hid[HD / 2];

    // cooperative W1 load (padded row 67 = 0)
    for (int k = tid; k < KP * HD; k += 256)
        s_W1[k] = (k < KD * HD) ? W1[k] : 0.f;

    if (B < NG * gpb) {
        const int grp = B / gpb;
        const int gb  = B % gpb;
        unsigned long long barn = 0;

        const float w2c = W2[tcol * HD + (HD - 1)];
        const float bb  = b1[tcol];

        // per-lane GEMM constants: output cols lane*4 .. lane*4+3
        const float4 bb4  = ((const float4*)b1)[lane];
        const float  w2a0 = W2[(lane * 4 + 0) * HD + (HD - 1)];
        const float  w2a1 = W2[(lane * 4 + 1) * HD + (HD - 1)];
        const float  w2a2 = W2[(lane * 4 + 2) * HD + (HD - 1)];
        const float  w2a3 = W2[(lane * 4 + 3) * HD + (HD - 1)];

        const int t0 = grp;
        const float*  xt  = x + (size_t)t0 * NN * FD;
        const float2* xt2 = (const float2*)xt;
        const int*    eit = ei + (size_t)t0 * 2 * NE;

        // ---- P0: membership init (flags/isc/cnt/packed) ----
        for (int j = tid; j < CT; j += 256) s_tgt[j] = tgt[t0 * CT + j];
        __syncthreads();
        for (int i = gb * 256 + tid; i < NN; i += gpb * 256) {
            int m = 0;
            #pragma unroll 8
            for (int j = 0; j < CT; j++) m |= (s_tgt[j] == i);
            g_flagA[grp][i] = m;
            g_flagB[grp][i] = m;
            g_isc[grp][i]   = m;
            g_cnt[grp][i]   = 0;
        }
        if (gb == 0 && tid == 0) g_packed[grp] = 0ull;
        gbar(grp, ++barn * (unsigned long long)gpb);

        // ---- P1: hop 1 (A->B) + ELL fill, 4 edges/iter for MLP ----
        {
            const int4* src4 = (const int4*)eit;
            const int4* dst4 = (const int4*)(eit + NE);
            for (int e4 = gb * 256 + tid; e4 < NE / 4; e4 += gpb * 256) {
                int4 s4 = src4[e4];
                int4 d4 = dst4[e4];
                int sl0 = atomicAdd(&g_cnt[grp][d4.x], 1);
                int sl1 = atomicAdd(&g_cnt[grp][d4.y], 1);
                int sl2 = atomicAdd(&g_cnt[grp][d4.z], 1);
                int sl3 = atomicAdd(&g_cnt[grp][d4.w], 1);
                if (sl0 < EC) g_ell[grp][d4.x * EC + sl0] = s4.x;
                if (sl1 < EC) g_ell[grp][d4.y * EC + sl1] = s4.y;
                if (sl2 < EC) g_ell[grp][d4.z * EC + sl2] = s4.z;
                if (sl3 < EC) g_ell[grp][d4.w * EC + sl3] = s4.w;
                int fs0 = g_flagA[grp][s4.x], fd0 = g_flagA[grp][d4.x];
                int fs1 = g_flagA[grp][s4.y], fd1 = g_flagA[grp][d4.y];
                int fs2 = g_flagA[grp][s4.z], fd2 = g_flagA[grp][d4.z];
                int fs3 = g_flagA[grp][s4.w], fd3 = g_flagA[grp][d4.w];
                if (fs0) g_flagB[grp][d4.x] = 1;
                if (fd0) g_flagB[grp][s4.x] = 1;
                if (fs1) g_flagB[grp][d4.y] = 1;
                if (fd1) g_flagB[grp][s4.y] = 1;
                if (fs2) g_flagB[grp][d4.z] = 1;
                if (fd2) g_flagB[grp][s4.z] = 1;
                if (fs3) g_flagB[grp][d4.w] = 1;
                if (fd3) g_flagB[grp][s4.w] = 1;
            }
        }
        gbar(grp, ++barn * gpb);

        // ---- P2: hop 2 (B->A), 4 edges/iter ----
        {
            const int4* src4 = (const int4*)eit;
            const int4* dst4 = (const int4*)(eit + NE);
            for (int e4 = gb * 256 + tid; e4 < NE / 4; e4 += gpb * 256) {
                int4 s4 = src4[e4];
                int4 d4 = dst4[e4];
                int fs0 = g_flagB[grp][s4.x], fd0 = g_flagB[grp][d4.x];
                int fs1 = g_flagB[grp][s4.y], fd1 = g_flagB[grp][d4.y];
                int fs2 = g_flagB[grp][s4.z], fd2 = g_flagB[grp][d4.z];
                int fs3 = g_flagB[grp][s4.w], fd3 = g_flagB[grp][d4.w];
                if (fs0) g_flagA[grp][d4.x] = 1;
                if (fd0) g_flagA[grp][s4.x] = 1;
                if (fs1) g_flagA[grp][d4.y] = 1;
                if (fd1) g_flagA[grp][s4.y] = 1;
                if (fs2) g_flagA[grp][d4.z] = 1;
                if (fd2) g_flagA[grp][s4.z] = 1;
                if (fs3) g_flagA[grp][d4.w] = 1;
                if (fd3) g_flagA[grp][s4.w] = 1;
            }
        }
        gbar(grp, ++barn * gpb);

        // ---- P3: deg -> dinv (sign-packed with is_center) + selfn ----
        for (int i = gb * 8 + wid; i < NN; i += gpb * 8) {
            if (!g_flagA[grp][i]) {
                if (lane == 0) { g_dinvs[grp][i] = 0.f; g_selfn[grp][i] = 0.f; }
                continue;
            }
            int c = g_cnt[grp][i]; if (c > EC) c = EC;
            const int* row = &g_ell[grp][i * EC];
            int deg = 0;
            for (int e = lane; e < c; e += 32)
                deg += g_flagA[grp][row[e]];
            #pragma unroll
            for (int o2 = 16; o2; o2 >>= 1)
                deg += __shfl_down_sync(~0u, deg, o2);
            if (lane == 0) {
                float di = rsqrtf((float)deg + 1.0f);
                g_dinvs[grp][i] = g_isc[grp][i] ? -di : di;
                g_selfn[grp][i] = di * di;
            }
        }
        gbar(grp, ++barn * gpb);

        // ---- P4: warp-autonomous gather + warp-local W1 GEMM + sv ----
        // Each warp owns node i end-to-end: no __syncthreads, no cross-warp
        // load imbalance. Lane computes output cols lane*4..lane*4+3.
        for (int i = gb * 8 + wid; i < NN; i += gpb * 8) {
            float dv = g_dinvs[grp][i];
            if (dv == 0.f) {
                if (lane == 0) g_svd[grp][i] = 0.f;
                continue;
            }
            gather_row(xt2, grp, i, szrow[wid], lane);
            __syncwarp();

            float a0 = bb4.x, a1 = bb4.y, a2 = bb4.z, a3 = bb4.w;
            const float*  zr = szrow[wid];
            const float4* wr = (const float4*)s_W1;
            #pragma unroll 1
            for (int k = 0; k < KP; k += 4) {
                float4 z = *(const float4*)&zr[k];
                float4 w0 = wr[(k + 0) * (HD / 4) + lane];
                float4 w1 = wr[(k + 1) * (HD / 4) + lane];
                float4 w2 = wr[(k + 2) * (HD / 4) + lane];
                float4 w3 = wr[(k + 3) * (HD / 4) + lane];
                a0 += z.x * w0.x + z.y * w1.x + z.z * w2.x + z.w * w3.x;
                a1 += z.x * w0.y + z.y * w1.y + z.z * w2.y + z.w * w3.y;
                a2 += z.x * w0.z + z.y * w1.z + z.z * w2.z + z.w * w3.z;
                a3 += z.x * w0.w + z.y * w1.w + z.z * w2.w + z.w * w3.w;
            }
            float p = fmaxf(a0, 0.f) * w2a0 + fmaxf(a1, 0.f) * w2a1
                    + fmaxf(a2, 0.f) * w2a2 + fmaxf(a3, 0.f) * w2a3;
            #pragma unroll
            for (int o2 = 16; o2; o2 >>= 1)
                p += __shfl_down_sync(~0u, p, o2);
            if (lane == 0) {
                g_sv[grp][i]  = p;
                g_svd[grp][i] = p * fabsf(dv);
            }
            __syncwarp();
        }
        gbar(grp, ++barn * gpb);

        // ---- P5: scalar layer-2 gather + argmax ----
        {
            const float b2h = b2[HD - 1];
            for (int i = gb * 8 + wid; i < NN; i += gpb * 8) {
                if (!g_flagA[grp][i]) continue;
                int c = g_cnt[grp][i]; if (c > EC) c = EC;
                const int* row = &g_ell[grp][i * EC];
                float acc = 0.f;
                for (int e = lane; e < c; e += 32)
                    acc += g_svd[grp][row[e]];
                #pragma unroll
                for (int o2 = 16; o2; o2 >>= 1)
                    acc += __shfl_down_sync(~0u, acc, o2);
                if (lane == 0) {
                    float v = acc * fabsf(g_dinvs[grp][i])
                            + g_sv[grp][i] * g_selfn[grp][i] + b2h;
                    v = fmaxf(v, 0.f);   // >=0: bits monotone as unsigned
                    unsigned long long key =
                        ((unsigned long long)__float_as_uint(v) << 32) |
                        (unsigned long long)(0xFFFFFFFFu - (unsigned)i);
                    atomicMax(&g_packed[grp], key);
                }
            }
        }
        gbar(grp, ++barn * gpb);

        // ---- P6 (gb 0): top-node layer2 recompute + seq + gi ----
        if (gb == 0) {
            if (tid == 0) {
                s_top = (int)(0xFFFFFFFFu -
                              (unsigned)(g_packed[grp] & 0xFFFFFFFFull));
                s_m = 0;
            }
            __syncthreads();
            int top = s_top;
            float dtop = fabsf(g_dinvs[grp][top]);
            int ctp = g_cnt[grp][top]; if (ctp > EC) ctp = EC;
            const int* rowT = &g_ell[grp][top * EC];
            for (int e = tid; e < ctp; e += 256) {
                int s = rowT[e];
                float w = fabsf(g_dinvs[grp][s]) * dtop;
                if (w != 0.f) {
                    int p = atomicAdd(&s_m, 1);
                    if (p < LM - 1) { s_list[p] = s; s_wl[p] = w; }
                }
            }
            __syncthreads();
            if (tid == 0) {
                int p = s_m; if (p > LM - 1) p = LM - 1;
                s_list[p] = top; s_wl[p] = g_selfn[grp][top];
                s_m = p + 1;
            }
            __syncthreads();
            int m = s_m;
            float z2acc = 0.f;
            for (int b0 = 0; b0 < m; b0 += 8) {
                int r = b0 + wid;
                if (r < m) gather_row(xt2, grp, s_list[r], szrow[wid], lane);
                __syncthreads();
                float acc0 = bb, acc1 = bb, acc2 = bb, acc3 = bb;
                const int h4 = half * 4;
                #pragma unroll 1
                for (int k = 0; k < KP; k += 4) {
                    float4 z0 = *(const float4*)&szrow[h4 + 0][k];
                    float4 z1 = *(const float4*)&szrow[h4 + 1][k];
                    float4 z2 = *(const float4*)&szrow[h4 + 2][k];
                    float4 z3 = *(const float4*)&szrow[h4 + 3][k];
                    float wa  = s_W1[(k + 0) * HD + tcol];
                    float wb  = s_W1[(k + 1) * HD + tcol];
                    float wcv = s_W1[(k + 2) * HD + tcol];
                    float wd  = s_W1[(k + 3) * HD + tcol];
                    acc0 += z0.x * wa + z0.y * wb + z0.z * wcv + z0.w * wd;
                    acc1 += z1.x * wa + z1.y * wb + z1.z * wcv + z1.w * wd;
                    acc2 += z2.x * wa + z2.y * wb + z2.z * wcv + z2.w * wd;
                    acc3 += z3.x * wa + z3.y * wb + z3.z * wcv + z3.w * wd;
                }
                float av[4] = {acc0, acc1, acc2, acc3};
                #pragma unroll
                for (int rr = 0; rr < 4; rr++) {
                    int gidx = b0 + h4 + rr;
                    if (gidx < m)
                        z2acc += fmaxf(av[rr], 0.f) * s_wl[gidx];
                }
                __syncthreads();
            }
            if (half == 1) s_z2[tcol] = z2acc;
            __syncthreads();
            if (half == 0) s_z2[tcol] = z2acc + s_z2[tcol];
            __syncthreads();
            if (tid < HD) {
                float a = b2[tid];
                #pragma unroll 8
                for (int k = 0; k < HD; k++) a += s_z2[k] * W2[k * HD + tid];
                float sq = fmaxf(a, 0.f);
                g_seq[t0 * HD + tid] = sq;
                s_sq[tid] = sq;
            }
            __syncthreads();
            for (int j = wid; j < 3 * HD; j += 8) {
                float dotv = 0.f;
                for (int k = lane; k < HD; k += 32)
                    dotv += Wih[j * HD + k] * s_sq[k];
                #pragma unroll
                for (int o2 = 16; o2; o2 >>= 1)
                    dotv += __shfl_down_sync(~0u, dotv, o2);
                if (lane == 0) g_gi[t0][j] = dotv + bih[j];
            }
        }
    }

    // ---- final: all blocks arrive; block 0 runs GRU + head ----
    if (B != 0) {
        __syncthreads();
        if (tid == 0) { __threadfence(); atomicAdd(&g_done, 1ull); }
        return;
    }
    if (tid == 0) {
        while (*((volatile unsigned long long*)&g_done) <
               (unsigned long long)(G - 1))
            __nanosleep(128);
        __threadfence();
    }
    __syncthreads();

    if (tid < HD) s_h[tid] = 0.f;
    __syncthreads();
    for (int t = 0; t < TS; t++) {
        for (int j = wid; j < 3 * HD; j += 8) {
            float dotv = 0.f;
            for (int k = lane; k < HD; k += 32)
                dotv += Whh[j * HD + k] * s_h[k];
            #pragma unroll
            for (int o2 = 16; o2; o2 >>= 1)
                dotv += __shfl_down_sync(~0u, dotv, o2);
            if (lane == 0) s_gh[j] = dotv + bhh[j];
        }
        __syncthreads();
        if (tid < HD) {
            float r  = 1.f / (1.f + expf(-(g_gi[t][tid] + s_gh[tid])));
            float z  = 1.f / (1.f + expf(-(g_gi[t][HD + tid] + s_gh[HD + tid])));
            float n2 = tanhf(g_gi[t][2 * HD + tid] + r * s_gh[2 * HD + tid]);
            s_h[tid] = (1.f - z) * n2 + z * s_h[tid];
        }
        __syncthreads();
    }
    if (tid < HD / 2) {
        float a = bc1[tid];
        #pragma unroll 8
        for (int k = 0; k < HD; k++) a += s_h[k] * Wc1[k * (HD / 2) + tid];
        s_hid[tid] = fmaxf(a, 0.f);
    }
    __syncthreads();
    if (tid == 0) {
        float a = bc2[0];
        for (int m2 = 0; m2 < HD / 2; m2++) a += s_hid[m2] * Wc2[m2];
        out[0] = 1.f / (1.f + expf(-a));
    }
}

// ---------------- launch -----------------------------------------------------

extern "C" void kernel_launch(void* const* d_in, const int* in_sizes, int n_in,
                              void* d_out, int out_size) {
    const float* x   = (const float*)d_in[0];
    const int*   ei  = (const int*)  d_in[1];
    const int*   tgt = (const int*)  d_in[2];
    const float* W1  = (const float*)d_in[3];
    const float* b1  = (const float*)d_in[4];
    const float* W2  = (const float*)d_in[5];
    const float* b2  = (const float*)d_in[6];
    const float* Wih = (const float*)d_in[7];
    const float* Whh = (const float*)d_in[8];
    const float* bih = (const float*)d_in[9];
    const float* bhh = (const float*)d_in[10];
    const float* Wc1 = (const float*)d_in[11];
    const float* bc1 = (const float*)d_in[12];
    const float* Wc2 = (const float*)d_in[13];
    const float* bc2 = (const float*)d_in[14];
    float* out = (float*)d_out;

    int dev = 0;
    cudaGetDevice(&dev);
    int nsm = 0;
    cudaDeviceGetAttribute(&nsm, cudaDevAttrMultiProcessorCount, dev);
    int perSM = 0;
    cudaOccupancyMaxActiveBlocksPerMultiprocessor(&perSM, k_mega, 256, 0);
    if (perSM < 1) perSM = 1;
    int G = nsm * perSM;
    if (G < NG) G = NG;
    if (G > NG * 256) G = NG * 256;

    k_pre<<<1, 128>>>();
    k_mega<<<G, 256>>>(x, ei, tgt, W1, b1, W2, b2,
                       Wih, Whh, bih, bhh, Wc1, bc1, Wc2, bc2, out);
}